// round 1
// baseline (speedup 1.0000x reference)
#include <cuda_runtime.h>
#include <cuda_bf16.h>

#define NMAX   100000
#define F_IN   128
#define HDIM   16
#define EMB    100
#define AA     5
#define HID    128

// -------- scratch (device globals; no allocation allowed) --------
__device__ float g_deg [NMAX];          // deg, then dinv in-place
__device__ float g_h1p [NMAX * HDIM];   // x @ W1
__device__ float g_agg1[NMAX * HDIM];
__device__ float g_h2p [NMAX * HDIM];   // relu(layer1) @ W2
__device__ float g_agg2[NMAX * HDIM];
__device__ float g_h2  [NMAX * HDIM];   // relu(layer2)  (pre-W3 space)
__device__ float g_agg3[AA * HDIM];     // layer-3 aggregation at the 5 pos nodes
__device__ unsigned char g_need1[NMAX];
__device__ unsigned char g_need2[NMAX];

// -------- init: deg=1 (self loop), bitmaps=0, agg3=0 --------
__global__ void k_init(int n) {
    int i = blockIdx.x * blockDim.x + threadIdx.x;
    if (i < n) {
        g_deg[i] = 1.0f;
        g_need1[i] = 0;
        g_need2[i] = 0;
    }
    if (i < AA * HDIM) g_agg3[i] = 0.0f;
}

// -------- fused: deg accumulation + mark sources of edges into pos-set --------
__global__ void k_deg_markA(const int* __restrict__ src, const int* __restrict__ dst,
                            const float* __restrict__ ew, const int* __restrict__ pos, int E) {
    int i = blockIdx.x * blockDim.x + threadIdx.x;
    if (i < AA) {                       // pos nodes themselves need layer-2 output (self loop)
        int p = __ldg(pos + i);
        if (p >= 0) g_need2[p] = 1;
    }
    if (i >= E) return;
    int d = dst[i];
    float w = ew[i];
    atomicAdd(&g_deg[d], w);
    int p0 = __ldg(pos + 0), p1 = __ldg(pos + 1), p2 = __ldg(pos + 2),
        p3 = __ldg(pos + 3), p4 = __ldg(pos + 4);
    if (d == p0 || d == p1 || d == p2 || d == p3 || d == p4) {
        g_need2[src[i]] = 1;
    }
}

__global__ void k_rsqrt(int n) {
    int i = blockIdx.x * blockDim.x + threadIdx.x;
    if (i < n) g_deg[i] = rsqrtf(g_deg[i]);   // deg >= 1 always (self loop weight 1)
}

// -------- h1p = x @ W1  (100000x128 @ 128x16), 32 nodes / 256-thread block --------
__global__ void k_gemm1(const float* __restrict__ x, const float* __restrict__ W1, int n) {
    __shared__ float xs[32 * 128];
    __shared__ float ws[128 * HDIM];
    int t = threadIdx.x;
    int n0 = blockIdx.x * 32;
#pragma unroll
    for (int k = 0; k < 16; k++) {
        int idx = t + k * 256;
        int r = idx >> 7, c = idx & 127;
        int node = n0 + r;
        xs[idx] = (node < n) ? x[(long)node * F_IN + c] : 0.0f;
    }
#pragma unroll
    for (int k = 0; k < 8; k++) {
        int idx = t + k * 256;
        ws[idx] = W1[idx];
    }
    __syncthreads();
#pragma unroll
    for (int u = 0; u < 2; u++) {
        int item = t + u * 256;
        int r = item >> 4, o = item & 15;
        float acc = 0.0f;
#pragma unroll 16
        for (int j = 0; j < F_IN; j++)
            acc = fmaf(xs[r * F_IN + j], ws[j * HDIM + o], acc);
        int node = n0 + r;
        if (node < n) g_h1p[node * HDIM + o] = acc;
    }
}

// -------- mark layer-1 frontier: sources of edges into needed2 nodes --------
__global__ void k_markB(const int* __restrict__ src, const int* __restrict__ dst, int E) {
    int i = blockIdx.x * blockDim.x + threadIdx.x;
    if (i >= E) return;
    if (g_need2[dst[i]]) g_need1[src[i]] = 1;
}

// -------- prep: need1 |= need2; zero only the needed agg rows --------
__global__ void k_prep(int n) {
    int i = blockIdx.x * blockDim.x + threadIdx.x;
    if (i >= n) return;
    unsigned char n2 = g_need2[i];
    unsigned char n1 = (unsigned char)(g_need1[i] | n2);
    g_need1[i] = n1;
    float4 z = make_float4(0.f, 0.f, 0.f, 0.f);
    if (n1) {
        float4* p = (float4*)(g_agg1 + i * HDIM);
        p[0] = z; p[1] = z; p[2] = z; p[3] = z;
    }
    if (n2) {
        float4* p = (float4*)(g_agg2 + i * HDIM);
        p[0] = z; p[1] = z; p[2] = z; p[3] = z;
    }
}

// -------- gated 16-dim edge scatter (layer selects buffers) --------
__global__ void k_edge(const int* __restrict__ src, const int* __restrict__ dst,
                       const float* __restrict__ ew, int E, int layer) {
    int i = blockIdx.x * blockDim.x + threadIdx.x;
    if (i >= E) return;
    int d = dst[i];
    const unsigned char* gate = (layer == 1) ? g_need1 : g_need2;
    if (!gate[d]) return;
    int s = src[i];
    float nrm = g_deg[s] * ew[i] * g_deg[d];
    const float* hin = (layer == 1) ? g_h1p : g_h2p;
    float* agg = (layer == 1) ? g_agg1 : g_agg2;
    const float4* h = (const float4*)(hin + s * HDIM);
    float* ag = agg + d * HDIM;
#pragma unroll
    for (int v = 0; v < 4; v++) {
        float4 hv = __ldg(h + v);
        atomicAdd(ag + v * 4 + 0, nrm * hv.x);
        atomicAdd(ag + v * 4 + 1, nrm * hv.y);
        atomicAdd(ag + v * 4 + 2, nrm * hv.z);
        atomicAdd(ag + v * 4 + 3, nrm * hv.w);
    }
}

// -------- node layer 1: h1 = relu(agg1 + dinv^2*h1p + b1); h2p = h1 @ W2 --------
__global__ void k_node1(const float* __restrict__ b1, const float* __restrict__ W2, int n) {
    int i = blockIdx.x * blockDim.x + threadIdx.x;
    if (i >= n) return;
    if (!g_need1[i]) return;
    float di = g_deg[i];
    float d2 = di * di;
    float h[HDIM];
#pragma unroll
    for (int k = 0; k < HDIM; k++)
        h[k] = fmaxf(g_agg1[i * HDIM + k] + d2 * g_h1p[i * HDIM + k] + __ldg(b1 + k), 0.0f);
#pragma unroll
    for (int o = 0; o < HDIM; o++) {
        float acc = 0.0f;
#pragma unroll
        for (int k = 0; k < HDIM; k++)
            acc = fmaf(h[k], __ldg(W2 + k * HDIM + o), acc);
        g_h2p[i * HDIM + o] = acc;
    }
}

// -------- node layer 2: h2 = relu(agg2 + dinv^2*h2p + b2) --------
__global__ void k_node2(const float* __restrict__ b2, int n) {
    int i = blockIdx.x * blockDim.x + threadIdx.x;
    if (i >= n) return;
    if (!g_need2[i]) return;
    float di = g_deg[i];
    float d2 = di * di;
#pragma unroll
    for (int k = 0; k < HDIM; k++)
        g_h2[i * HDIM + k] =
            fmaxf(g_agg2[i * HDIM + k] + d2 * g_h2p[i * HDIM + k] + __ldg(b2 + k), 0.0f);
}

// -------- layer-3 edge pass: only edges whose dst is one of the 5 pos nodes --------
__global__ void k_edge3(const int* __restrict__ src, const int* __restrict__ dst,
                        const float* __restrict__ ew, const int* __restrict__ pos, int E) {
    int i = blockIdx.x * blockDim.x + threadIdx.x;
    if (i >= E) return;
    int d = dst[i];
    int p[AA];
#pragma unroll
    for (int a = 0; a < AA; a++) p[a] = __ldg(pos + a);
    bool hit = false;
#pragma unroll
    for (int a = 0; a < AA; a++) hit = hit || (d == p[a]);
    if (!hit) return;
    int s = src[i];
    float nrm = g_deg[s] * ew[i] * g_deg[d];
    float hv[HDIM];
    const float4* h = (const float4*)(g_h2 + s * HDIM);
#pragma unroll
    for (int v = 0; v < 4; v++) {
        float4 q = __ldg(h + v);
        hv[v * 4 + 0] = q.x; hv[v * 4 + 1] = q.y; hv[v * 4 + 2] = q.z; hv[v * 4 + 3] = q.w;
    }
#pragma unroll
    for (int a = 0; a < AA; a++) {
        if (d == p[a]) {
#pragma unroll
            for (int k = 0; k < HDIM; k++)
                atomicAdd(&g_agg3[a * HDIM + k], nrm * hv[k]);
        }
    }
}

// -------- head: project agg3 by W3, flatten, 3-layer MLP -> out[5] --------
__global__ void k_head(const int* __restrict__ pos,
                       const float* __restrict__ W3, const float* __restrict__ b3,
                       const float* __restrict__ fcW1, const float* __restrict__ fcb1,
                       const float* __restrict__ fcW2, const float* __restrict__ fcb2,
                       const float* __restrict__ fcW3, const float* __restrict__ fcb3,
                       float* __restrict__ out) {
    __shared__ float v[AA * HDIM];
    __shared__ float z[AA * EMB];
    __shared__ float o1[HID];
    __shared__ float o2[HID];
    int t = threadIdx.x;

    if (t < AA * HDIM) {
        int a = t >> 4, k = t & 15;
        int p = __ldg(pos + a);
        float val = 0.0f;
        if (p >= 0) {
            float di = g_deg[p];
            val = g_agg3[t] + di * di * g_h2[p * HDIM + k];   // add self-loop term
        }
        v[t] = val;
    }
    __syncthreads();

    for (int j = t; j < AA * EMB; j += blockDim.x) {
        int a = j / EMB, c = j % EMB;
        int p = __ldg(pos + a);
        float acc;
        if (p < 0) {
            acc = -1.0f;                                       // pos==-1 -> all -1 embedding
        } else {
            acc = __ldg(b3 + c);
#pragma unroll
            for (int k = 0; k < HDIM; k++)
                acc = fmaf(v[a * HDIM + k], __ldg(W3 + k * EMB + c), acc);
        }
        z[j] = acc;
    }
    __syncthreads();

    if (t < HID) {
        float acc = __ldg(fcb1 + t);
#pragma unroll 4
        for (int j = 0; j < AA * EMB; j++)
            acc = fmaf(z[j], __ldg(fcW1 + j * HID + t), acc);
        o1[t] = fmaxf(acc, 0.0f);
    }
    __syncthreads();

    if (t < HID) {
        float acc = __ldg(fcb2 + t);
#pragma unroll 4
        for (int j = 0; j < HID; j++)
            acc = fmaf(o1[j], __ldg(fcW2 + j * HID + t), acc);
        o2[t] = fmaxf(acc, 0.0f);
    }
    __syncthreads();

    if (t < AA) {
        float acc = __ldg(fcb3 + t);
#pragma unroll 4
        for (int j = 0; j < HID; j++)
            acc = fmaf(o2[j], __ldg(fcW3 + j * AA + t), acc);
        out[t] = acc;
    }
}

extern "C" void kernel_launch(void* const* d_in, const int* in_sizes, int n_in,
                              void* d_out, int out_size) {
    const float* x    = (const float*)d_in[0];
    const int*   ei   = (const int*)  d_in[1];
    const float* ew   = (const float*)d_in[2];
    const int*   pos  = (const int*)  d_in[3];
    const float* W1   = (const float*)d_in[4];
    const float* b1   = (const float*)d_in[5];
    const float* W2   = (const float*)d_in[6];
    const float* b2   = (const float*)d_in[7];
    const float* W3   = (const float*)d_in[8];
    const float* b3   = (const float*)d_in[9];
    const float* fcW1 = (const float*)d_in[10];
    const float* fcb1 = (const float*)d_in[11];
    const float* fcW2 = (const float*)d_in[12];
    const float* fcb2 = (const float*)d_in[13];
    const float* fcW3 = (const float*)d_in[14];
    const float* fcb3 = (const float*)d_in[15];

    int N = in_sizes[0] / F_IN;
    int E = in_sizes[1] / 2;
    const int* src = ei;
    const int* dst = ei + E;
    float* out = (float*)d_out;

    const int TB = 256;
    int nbN = (N + TB - 1) / TB;
    int nbE = (E + TB - 1) / TB;

    k_init     <<<nbN, TB>>>(N);
    k_deg_markA<<<nbE, TB>>>(src, dst, ew, pos, E);
    k_rsqrt    <<<nbN, TB>>>(N);
    k_gemm1    <<<(N + 31) / 32, 256>>>(x, W1, N);
    k_markB    <<<nbE, TB>>>(src, dst, E);
    k_prep     <<<nbN, TB>>>(N);
    k_edge     <<<nbE, TB>>>(src, dst, ew, E, 1);
    k_node1    <<<nbN, TB>>>(b1, W2, N);
    k_edge     <<<nbE, TB>>>(src, dst, ew, E, 2);
    k_node2    <<<nbN, TB>>>(b2, N);
    k_edge3    <<<nbE, TB>>>(src, dst, ew, pos, E);
    k_head     <<<1, 128>>>(pos, W3, b3, fcW1, fcb1, fcW2, fcb2, fcW3, fcb3, out);
}

// round 2
// speedup vs baseline: 1.0777x; 1.0777x over previous
#include <cuda_runtime.h>
#include <cuda_bf16.h>

#define NMAX   100000
#define ECAP   3300000
#define F_IN   128
#define HDIM   16
#define EMB    100
#define AA     5
#define HID    128

// -------- scratch (device globals; no allocation allowed) --------
__device__ float g_deg [NMAX];          // deg, then dinv in-place
__device__ float g_h1p [NMAX * HDIM];   // x @ W1
__device__ float g_agg1[NMAX * HDIM];
__device__ float g_h2p [NMAX * HDIM];   // relu(layer1) @ W2
__device__ float g_agg2[NMAX * HDIM];
__device__ float g_h2  [NMAX * HDIM];   // relu(layer2)
__device__ float g_agg3[AA * HDIM];
__device__ unsigned char g_need1[NMAX];
__device__ unsigned char g_need2[NMAX];
__device__ int g_list2[ECAP];           // edges into need2 nodes (~5k)
__device__ int g_list3[ECAP];           // edges into pos nodes (~160)
__device__ int g_cnt2;
__device__ int g_cnt3;

// -------- init --------
__global__ void k_init(int n) {
    int i = blockIdx.x * blockDim.x + threadIdx.x;
    if (i < n) {
        g_deg[i] = 1.0f;       // self-loop weight
        g_need1[i] = 0;
        g_need2[i] = 0;
    }
    if (i < AA * HDIM) g_agg3[i] = 0.0f;
    if (i == 0) { g_cnt2 = 0; g_cnt3 = 0; }
}

// -------- scan1: deg accumulate + mark need2 (in-neighbors of pos + pos) + build list3 --------
__global__ void k_scan1(const int* __restrict__ src, const int* __restrict__ dst,
                        const float* __restrict__ ew, const int* __restrict__ pos, int E) {
    int i = blockIdx.x * blockDim.x + threadIdx.x;
    if (i < AA) {
        int p = __ldg(pos + i);
        if (p >= 0) g_need2[p] = 1;
    }
    if (i >= E) return;
    int d = dst[i];
    atomicAdd(&g_deg[d], ew[i]);
    bool hit = false;
#pragma unroll
    for (int a = 0; a < AA; a++) hit = hit || (d == __ldg(pos + a));
    if (hit) {
        g_need2[src[i]] = 1;
        int k = atomicAdd(&g_cnt3, 1);
        if (k < ECAP) g_list3[k] = i;
    }
}

// -------- scan2: mark need1 = sources of edges into need2 + build list2 --------
__global__ void k_scan2(const int* __restrict__ src, const int* __restrict__ dst, int E) {
    int i = blockIdx.x * blockDim.x + threadIdx.x;
    if (i >= E) return;
    if (g_need2[dst[i]]) {
        g_need1[src[i]] = 1;
        int k = atomicAdd(&g_cnt2, 1);
        if (k < ECAP) g_list2[k] = i;
    }
}

// -------- prep: dinv = rsqrt(deg); need1 |= need2; zero needed agg rows --------
__global__ void k_prep(int n) {
    int i = blockIdx.x * blockDim.x + threadIdx.x;
    if (i >= n) return;
    g_deg[i] = rsqrtf(g_deg[i]);
    unsigned char n2 = g_need2[i];
    unsigned char n1 = (unsigned char)(g_need1[i] | n2);
    g_need1[i] = n1;
    float4 z = make_float4(0.f, 0.f, 0.f, 0.f);
    if (n1) {
        float4* p = (float4*)(g_agg1 + i * HDIM);
        p[0] = z; p[1] = z; p[2] = z; p[3] = z;
    }
    if (n2) {
        float4* p = (float4*)(g_agg2 + i * HDIM);
        p[0] = z; p[1] = z; p[2] = z; p[3] = z;
    }
}

// -------- h1p = x @ W1, vectorized: 64 nodes/block, 256 thr, 4 outputs/thread --------
#define GN 64
#define XPITCH 132   // padded row (floats) to avoid bank conflicts
__global__ void k_gemm1(const float* __restrict__ x, const float* __restrict__ W1, int n) {
    __shared__ float xs[GN * XPITCH];        // 33792 B
    __shared__ float ws[F_IN * HDIM];        //  8192 B
    int t = threadIdx.x;
    int n0 = blockIdx.x * GN;

#pragma unroll
    for (int k = 0; k < 8; k++) ws[t + k * 256] = W1[t + k * 256];

#pragma unroll
    for (int k = 0; k < 8; k++) {
        int f = t + k * 256;              // float4 index (64 rows * 32 f4/row)
        int r = f >> 5, c = f & 31;
        float4 v = make_float4(0.f, 0.f, 0.f, 0.f);
        int node = n0 + r;
        if (node < n) v = *(const float4*)(x + (size_t)node * F_IN + c * 4);
        *(float4*)(xs + r * XPITCH + c * 4) = v;
    }
    __syncthreads();

    int r  = t >> 2;          // node within block
    int og = (t & 3) * 4;     // output group
    const float* xr = xs + r * XPITCH;
    float4 acc = make_float4(0.f, 0.f, 0.f, 0.f);
#pragma unroll 8
    for (int j = 0; j < F_IN; j += 4) {
        float4 xv = *(const float4*)(xr + j);
        const float* wb = ws + j * HDIM + og;
        float4 w0 = *(const float4*)(wb);
        float4 w1 = *(const float4*)(wb + HDIM);
        float4 w2 = *(const float4*)(wb + 2 * HDIM);
        float4 w3 = *(const float4*)(wb + 3 * HDIM);
        acc.x = fmaf(xv.x, w0.x, acc.x); acc.y = fmaf(xv.x, w0.y, acc.y);
        acc.z = fmaf(xv.x, w0.z, acc.z); acc.w = fmaf(xv.x, w0.w, acc.w);
        acc.x = fmaf(xv.y, w1.x, acc.x); acc.y = fmaf(xv.y, w1.y, acc.y);
        acc.z = fmaf(xv.y, w1.z, acc.z); acc.w = fmaf(xv.y, w1.w, acc.w);
        acc.x = fmaf(xv.z, w2.x, acc.x); acc.y = fmaf(xv.z, w2.y, acc.y);
        acc.z = fmaf(xv.z, w2.z, acc.z); acc.w = fmaf(xv.z, w2.w, acc.w);
        acc.x = fmaf(xv.w, w3.x, acc.x); acc.y = fmaf(xv.w, w3.y, acc.y);
        acc.z = fmaf(xv.w, w3.z, acc.z); acc.w = fmaf(xv.w, w3.w, acc.w);
    }
    int node = n0 + r;
    if (node < n) *(float4*)(g_h1p + node * HDIM + og) = acc;
}

// -------- layer-1 edge scatter, gated on need1[dst] --------
__global__ void k_edge1(const int* __restrict__ src, const int* __restrict__ dst,
                        const float* __restrict__ ew, int E) {
    int i = blockIdx.x * blockDim.x + threadIdx.x;
    if (i >= E) return;
    int d = dst[i];
    if (!g_need1[d]) return;
    int s = src[i];
    float nrm = g_deg[s] * ew[i] * g_deg[d];
    const float4* h = (const float4*)(g_h1p + s * HDIM);
    float* ag = g_agg1 + d * HDIM;
#pragma unroll
    for (int v = 0; v < 4; v++) {
        float4 hv = __ldg(h + v);
        atomicAdd(ag + v * 4 + 0, nrm * hv.x);
        atomicAdd(ag + v * 4 + 1, nrm * hv.y);
        atomicAdd(ag + v * 4 + 2, nrm * hv.z);
        atomicAdd(ag + v * 4 + 3, nrm * hv.w);
    }
}

// -------- node layer 1: h1 = relu(agg1 + dinv^2*h1p + b1); h2p = h1 @ W2 --------
__global__ void k_node1(const float* __restrict__ b1, const float* __restrict__ W2, int n) {
    int i = blockIdx.x * blockDim.x + threadIdx.x;
    if (i >= n) return;
    if (!g_need1[i]) return;
    float di = g_deg[i];
    float d2 = di * di;
    float h[HDIM];
#pragma unroll
    for (int k = 0; k < HDIM; k++)
        h[k] = fmaxf(g_agg1[i * HDIM + k] + d2 * g_h1p[i * HDIM + k] + __ldg(b1 + k), 0.0f);
#pragma unroll
    for (int o = 0; o < HDIM; o++) {
        float acc = 0.0f;
#pragma unroll
        for (int k = 0; k < HDIM; k++)
            acc = fmaf(h[k], __ldg(W2 + k * HDIM + o), acc);
        g_h2p[i * HDIM + o] = acc;
    }
}

// -------- layer-2 edge scatter over compact list2 --------
__global__ void k_edge2(const int* __restrict__ src, const int* __restrict__ dst,
                        const float* __restrict__ ew) {
    int cnt = g_cnt2; if (cnt > ECAP) cnt = ECAP;
    int stride = gridDim.x * blockDim.x;
    for (int i = blockIdx.x * blockDim.x + threadIdx.x; i < cnt; i += stride) {
        int e = g_list2[i];
        int d = dst[e], s = src[e];
        float nrm = g_deg[s] * ew[e] * g_deg[d];
        const float4* h = (const float4*)(g_h2p + s * HDIM);
        float* ag = g_agg2 + d * HDIM;
#pragma unroll
        for (int v = 0; v < 4; v++) {
            float4 hv = __ldg(h + v);
            atomicAdd(ag + v * 4 + 0, nrm * hv.x);
            atomicAdd(ag + v * 4 + 1, nrm * hv.y);
            atomicAdd(ag + v * 4 + 2, nrm * hv.z);
            atomicAdd(ag + v * 4 + 3, nrm * hv.w);
        }
    }
}

// -------- node layer 2: h2 = relu(agg2 + dinv^2*h2p + b2) --------
__global__ void k_node2(const float* __restrict__ b2, int n) {
    int i = blockIdx.x * blockDim.x + threadIdx.x;
    if (i >= n) return;
    if (!g_need2[i]) return;
    float di = g_deg[i];
    float d2 = di * di;
#pragma unroll
    for (int k = 0; k < HDIM; k++)
        g_h2[i * HDIM + k] =
            fmaxf(g_agg2[i * HDIM + k] + d2 * g_h2p[i * HDIM + k] + __ldg(b2 + k), 0.0f);
}

// -------- layer-3 edge scatter over compact list3 into 5 pos accumulators --------
__global__ void k_edge3(const int* __restrict__ src, const int* __restrict__ dst,
                        const float* __restrict__ ew, const int* __restrict__ pos) {
    int cnt = g_cnt3; if (cnt > ECAP) cnt = ECAP;
    int stride = gridDim.x * blockDim.x;
    for (int i = blockIdx.x * blockDim.x + threadIdx.x; i < cnt; i += stride) {
        int e = g_list3[i];
        int d = dst[e], s = src[e];
        float nrm = g_deg[s] * ew[e] * g_deg[d];
        float hv[HDIM];
        const float4* h = (const float4*)(g_h2 + s * HDIM);
#pragma unroll
        for (int v = 0; v < 4; v++) {
            float4 q = __ldg(h + v);
            hv[v*4+0]=q.x; hv[v*4+1]=q.y; hv[v*4+2]=q.z; hv[v*4+3]=q.w;
        }
#pragma unroll
        for (int a = 0; a < AA; a++) {
            if (d == __ldg(pos + a)) {
#pragma unroll
                for (int k = 0; k < HDIM; k++)
                    atomicAdd(&g_agg3[a * HDIM + k], nrm * hv[k]);
            }
        }
    }
}

// -------- head: W3 projection + 3-layer MLP -> out[5] --------
__global__ void k_head(const int* __restrict__ pos,
                       const float* __restrict__ W3, const float* __restrict__ b3,
                       const float* __restrict__ fcW1, const float* __restrict__ fcb1,
                       const float* __restrict__ fcW2, const float* __restrict__ fcb2,
                       const float* __restrict__ fcW3, const float* __restrict__ fcb3,
                       float* __restrict__ out) {
    __shared__ float v[AA * HDIM];
    __shared__ float z[AA * EMB];
    __shared__ float o1[HID];
    __shared__ float o2[HID];
    int t = threadIdx.x;

    if (t < AA * HDIM) {
        int a = t >> 4, k = t & 15;
        int p = __ldg(pos + a);
        float val = 0.0f;
        if (p >= 0) {
            float di = g_deg[p];
            val = g_agg3[t] + di * di * g_h2[p * HDIM + k];
        }
        v[t] = val;
    }
    __syncthreads();

    for (int j = t; j < AA * EMB; j += blockDim.x) {
        int a = j / EMB, c = j % EMB;
        int p = __ldg(pos + a);
        float acc;
        if (p < 0) {
            acc = -1.0f;
        } else {
            acc = __ldg(b3 + c);
#pragma unroll
            for (int k = 0; k < HDIM; k++)
                acc = fmaf(v[a * HDIM + k], __ldg(W3 + k * EMB + c), acc);
        }
        z[j] = acc;
    }
    __syncthreads();

    if (t < HID) {
        float acc = __ldg(fcb1 + t);
#pragma unroll 4
        for (int j = 0; j < AA * EMB; j++)
            acc = fmaf(z[j], __ldg(fcW1 + j * HID + t), acc);
        o1[t] = fmaxf(acc, 0.0f);
    }
    __syncthreads();

    if (t < HID) {
        float acc = __ldg(fcb2 + t);
#pragma unroll 4
        for (int j = 0; j < HID; j++)
            acc = fmaf(o1[j], __ldg(fcW2 + j * HID + t), acc);
        o2[t] = fmaxf(acc, 0.0f);
    }
    __syncthreads();

    if (t < AA) {
        float acc = __ldg(fcb3 + t);
#pragma unroll 4
        for (int j = 0; j < HID; j++)
            acc = fmaf(o2[j], __ldg(fcW3 + j * AA + t), acc);
        out[t] = acc;
    }
}

extern "C" void kernel_launch(void* const* d_in, const int* in_sizes, int n_in,
                              void* d_out, int out_size) {
    const float* x    = (const float*)d_in[0];
    const int*   ei   = (const int*)  d_in[1];
    const float* ew   = (const float*)d_in[2];
    const int*   pos  = (const int*)  d_in[3];
    const float* W1   = (const float*)d_in[4];
    const float* b1   = (const float*)d_in[5];
    const float* W2   = (const float*)d_in[6];
    const float* b2   = (const float*)d_in[7];
    const float* W3   = (const float*)d_in[8];
    const float* b3   = (const float*)d_in[9];
    const float* fcW1 = (const float*)d_in[10];
    const float* fcb1 = (const float*)d_in[11];
    const float* fcW2 = (const float*)d_in[12];
    const float* fcb2 = (const float*)d_in[13];
    const float* fcW3 = (const float*)d_in[14];
    const float* fcb3 = (const float*)d_in[15];

    int N = in_sizes[0] / F_IN;
    int E = in_sizes[1] / 2;
    const int* src = ei;
    const int* dst = ei + E;
    float* out = (float*)d_out;

    const int TB = 256;
    int nbN = (N + TB - 1) / TB;
    int nbE = (E + TB - 1) / TB;

    k_init <<<nbN, TB>>>(N);
    k_scan1<<<nbE, TB>>>(src, dst, ew, pos, E);
    k_scan2<<<nbE, TB>>>(src, dst, E);
    k_prep <<<nbN, TB>>>(N);
    k_gemm1<<<(N + GN - 1) / GN, 256>>>(x, W1, N);
    k_edge1<<<nbE, TB>>>(src, dst, ew, E);
    k_node1<<<nbN, TB>>>(b1, W2, N);
    k_edge2<<<128, TB>>>(src, dst, ew);
    k_node2<<<nbN, TB>>>(b2, N);
    k_edge3<<<32, TB>>>(src, dst, ew, pos);
    k_head <<<1, 128>>>(pos, W3, b3, fcW1, fcb1, fcW2, fcb2, fcW3, fcb3, out);
}